// round 1
// baseline (speedup 1.0000x reference)
#include <cuda_runtime.h>
#include <cuda_bf16.h>
#include <cstdint>

#define NN 50000
#define NE 600000
#define HIDD 128
#define AS 132                       // padded row stride (floats): conflict-free, float4-aligned
#define SMEM_WORDS (2*128*AS + 4*128)
#define SMEM_BYTES (SMEM_WORDS*4)
#define NB ((NN + 127) / 128)

// ---------------- device scratch (static, no runtime alloc) ----------------
__device__ __align__(16) float g_x1[(size_t)NN * HIDD];
__device__ __align__(16) float g_x2[(size_t)NN * HIDD];
__device__ int   g_deg[NN];
__device__ int   g_rowptr[NN + 1];
__device__ int   g_cursor[NN];
__device__ int   g_esrc[NE];
__device__ float g_tap[4 * HIDD];

// ---------------- helpers ----------------
__device__ __forceinline__ unsigned f2t(float f) {
    unsigned u;
    asm("cvt.rna.tf32.f32 %0, %1;" : "=r"(u) : "f"(f));
    return u;
}

__device__ __forceinline__ void mma8(float c[4], unsigned a0, unsigned a1, unsigned a2,
                                     unsigned a3, unsigned b0, unsigned b1) {
    asm volatile(
        "mma.sync.aligned.m16n8k8.row.col.f32.tf32.tf32.f32 "
        "{%0,%1,%2,%3},{%4,%5,%6,%7},{%8,%9},{%0,%1,%2,%3};"
        : "+f"(c[0]), "+f"(c[1]), "+f"(c[2]), "+f"(c[3])
        : "r"(a0), "r"(a1), "r"(a2), "r"(a3), "r"(b0), "r"(b1));
}

// ---------------- CSR build ----------------
__global__ void zero_k() {
    int i = blockIdx.x * blockDim.x + threadIdx.x;
    if (i < NN) g_deg[i] = 0;
    if (i < 4 * HIDD) g_tap[i] = 0.f;
}

__global__ void hist_k(const int* __restrict__ dst) {
    int i = blockIdx.x * blockDim.x + threadIdx.x;
    if (i < NE) atomicAdd(&g_deg[dst[i]], 1);
}

__global__ void scan_k() {
    __shared__ int part[1024];
    int t = threadIdx.x;
    const int chunk = (NN + 1023) / 1024;
    int lo = t * chunk;
    int hi = lo + chunk; if (hi > NN) hi = NN;
    int s = 0;
    for (int i = lo; i < hi; i++) s += g_deg[i];
    part[t] = s;
    __syncthreads();
    for (int off = 1; off < 1024; off <<= 1) {
        int v = 0;
        if (t >= off) v = part[t - off];
        __syncthreads();
        if (t >= off) part[t] += v;
        __syncthreads();
    }
    int run = (t == 0) ? 0 : part[t - 1];
    for (int i = lo; i < hi; i++) {
        g_rowptr[i] = run;
        g_cursor[i] = run;
        run += g_deg[i];
    }
    if (t == 1023) g_rowptr[NN] = NE;
}

__global__ void scatter_k(const int* __restrict__ src, const int* __restrict__ dst) {
    int i = blockIdx.x * blockDim.x + threadIdx.x;
    if (i < NE) {
        int d = dst[i];
        int pos = atomicAdd(&g_cursor[d], 1);
        g_esrc[pos] = src[i];
    }
}

// ---------------- fused GIN layer ----------------
// One block = 128 nodes. Phases: gather(+self) -> tf32 smem tile ->
// GEMM1 (BN folded, ReLU) -> GEMM2 (ReLU) -> global write + tap column sums.
__global__ __launch_bounds__(512, 1) void gin_layer(
    const float* __restrict__ Xext, int in_sel, int out_sel, int tap_off,
    const float* __restrict__ W1, const float* __restrict__ b1,
    const float* __restrict__ gam, const float* __restrict__ bet,
    const float* __restrict__ mu, const float* __restrict__ var,
    const float* __restrict__ W2, const float* __restrict__ b2)
{
    extern __shared__ unsigned sm[];
    unsigned* sA = sm;                  // 128 x AS tf32 tile (A, then H1)
    unsigned* sW = sm + 128 * AS;       // 128 x AS tf32 weights (W1', then W2)
    float* sB1    = (float*)(sm + 2 * 128 * AS);
    float* sB2    = sB1 + 128;
    float* sTap   = sB2 + 128;
    float* sScale = sTap + 128;

    const float* Xin = (in_sel == 0) ? Xext : (in_sel == 1 ? g_x1 : g_x2);
    float* Xout = (out_sel == 1) ? g_x1 : g_x2;
    float* tap = g_tap + tap_off;

    const int tid = threadIdx.x;
    const int w = tid >> 5, lane = tid & 31;
    const int rowBase = blockIdx.x * 128;

    if (tid < 128) {
        sScale[tid] = gam[tid] * rsqrtf(var[tid] + 1e-5f);
        sTap[tid] = 0.f;
    }
    __syncthreads();

    // --- load W1 with BN scale folded, bias fold ---
    for (int idx = tid; idx < 128 * 128; idx += 512) {
        int c = idx >> 7, k = idx & 127;
        sW[c * AS + k] = f2t(W1[idx] * sScale[c]);
    }
    if (tid < 128)
        sB1[tid] = (b1[tid] - mu[tid]) * sScale[tid] + bet[tid];

    // --- gather: each warp owns 8 rows ---
    const float4* X4 = (const float4*)Xin;
    for (int i = 0; i < 8; i++) {
        int lr = w * 8 + i;
        int n = rowBase + lr;
        float4 acc = make_float4(0.f, 0.f, 0.f, 0.f);
        if (n < NN) {
            acc = X4[(size_t)n * 32 + lane];           // +x_i (eps=0 GIN)
            int e = g_rowptr[n], e1 = g_rowptr[n + 1];
            for (; e + 4 <= e1; e += 4) {
                int s0 = g_esrc[e], s1 = g_esrc[e + 1];
                int s2 = g_esrc[e + 2], s3 = g_esrc[e + 3];
                float4 v0 = X4[(size_t)s0 * 32 + lane];
                float4 v1 = X4[(size_t)s1 * 32 + lane];
                float4 v2 = X4[(size_t)s2 * 32 + lane];
                float4 v3 = X4[(size_t)s3 * 32 + lane];
                acc.x += v0.x + v1.x + v2.x + v3.x;
                acc.y += v0.y + v1.y + v2.y + v3.y;
                acc.z += v0.z + v1.z + v2.z + v3.z;
                acc.w += v0.w + v1.w + v2.w + v3.w;
            }
            for (; e < e1; e++) {
                float4 v = X4[(size_t)g_esrc[e] * 32 + lane];
                acc.x += v.x; acc.y += v.y; acc.z += v.z; acc.w += v.w;
            }
        }
        uint4 u = make_uint4(f2t(acc.x), f2t(acc.y), f2t(acc.z), f2t(acc.w));
        *(uint4*)&sA[lr * AS + lane * 4] = u;
    }
    __syncthreads();

    // --- GEMM1: H1 = ReLU(A @ W1'^T + b1') ---
    const int wr = w & 7, wc = w >> 3;
    const int rb = wr * 16, cb = wc * 64;
    const int gq = lane >> 2, q = lane & 3;

    float acc1[8][4];
#pragma unroll
    for (int nt = 0; nt < 8; nt++)
#pragma unroll
        for (int j = 0; j < 4; j++) acc1[nt][j] = 0.f;

#pragma unroll
    for (int kt = 0; kt < 16; kt++) {
        int k0 = kt * 8 + q;
        unsigned a0 = sA[(rb + gq) * AS + k0];
        unsigned a1 = sA[(rb + gq + 8) * AS + k0];
        unsigned a2 = sA[(rb + gq) * AS + k0 + 4];
        unsigned a3 = sA[(rb + gq + 8) * AS + k0 + 4];
#pragma unroll
        for (int nt = 0; nt < 8; nt++) {
            int n0 = cb + nt * 8 + gq;
            unsigned b0 = sW[n0 * AS + k0];
            unsigned b1v = sW[n0 * AS + k0 + 4];
            mma8(acc1[nt], a0, a1, a2, a3, b0, b1v);
        }
    }
    __syncthreads();

    // --- H1 -> sA (tf32), W2 -> sW, b2 -> sB2 ---
#pragma unroll
    for (int nt = 0; nt < 8; nt++) {
        int c0 = cb + nt * 8 + q * 2;
        float o00 = fmaxf(acc1[nt][0] + sB1[c0], 0.f);
        float o01 = fmaxf(acc1[nt][1] + sB1[c0 + 1], 0.f);
        float o10 = fmaxf(acc1[nt][2] + sB1[c0], 0.f);
        float o11 = fmaxf(acc1[nt][3] + sB1[c0 + 1], 0.f);
        uint2 u0 = make_uint2(f2t(o00), f2t(o01));
        uint2 u1 = make_uint2(f2t(o10), f2t(o11));
        *(uint2*)&sA[(rb + gq) * AS + c0] = u0;
        *(uint2*)&sA[(rb + gq + 8) * AS + c0] = u1;
    }
    for (int idx = tid; idx < 128 * 128; idx += 512) {
        int c = idx >> 7, k = idx & 127;
        sW[c * AS + k] = f2t(W2[idx]);
    }
    if (tid < 128) sB2[tid] = b2[tid];
    __syncthreads();

    // --- GEMM2: H2 = ReLU(H1 @ W2^T + b2) ---
    float acc2[8][4];
#pragma unroll
    for (int nt = 0; nt < 8; nt++)
#pragma unroll
        for (int j = 0; j < 4; j++) acc2[nt][j] = 0.f;

#pragma unroll
    for (int kt = 0; kt < 16; kt++) {
        int k0 = kt * 8 + q;
        unsigned a0 = sA[(rb + gq) * AS + k0];
        unsigned a1 = sA[(rb + gq + 8) * AS + k0];
        unsigned a2 = sA[(rb + gq) * AS + k0 + 4];
        unsigned a3 = sA[(rb + gq + 8) * AS + k0 + 4];
#pragma unroll
        for (int nt = 0; nt < 8; nt++) {
            int n0 = cb + nt * 8 + gq;
            unsigned b0 = sW[n0 * AS + k0];
            unsigned b1v = sW[n0 * AS + k0 + 4];
            mma8(acc2[nt], a0, a1, a2, a3, b0, b1v);
        }
    }

    // --- epilogue: write Xout, accumulate per-layer tap column sums ---
    const int r0 = rowBase + rb + gq;
    const int r1 = r0 + 8;
    const bool m0v = (r0 < NN), m1v = (r1 < NN);
#pragma unroll
    for (int nt = 0; nt < 8; nt++) {
        int c0 = cb + nt * 8 + q * 2;
        float o00 = m0v ? fmaxf(acc2[nt][0] + sB2[c0], 0.f) : 0.f;
        float o01 = m0v ? fmaxf(acc2[nt][1] + sB2[c0 + 1], 0.f) : 0.f;
        float o10 = m1v ? fmaxf(acc2[nt][2] + sB2[c0], 0.f) : 0.f;
        float o11 = m1v ? fmaxf(acc2[nt][3] + sB2[c0 + 1], 0.f) : 0.f;
        if (m0v) *(float2*)&Xout[(size_t)r0 * 128 + c0] = make_float2(o00, o01);
        if (m1v) *(float2*)&Xout[(size_t)r1 * 128 + c0] = make_float2(o10, o11);
        atomicAdd(&sTap[c0], o00 + o10);
        atomicAdd(&sTap[c0 + 1], o01 + o11);
    }
    __syncthreads();
    if (tid < 128) atomicAdd(&tap[tid], sTap[tid]);
}

// ---------------- readout ----------------
__global__ void readout_k(const float* __restrict__ Wll, const float* __restrict__ bll,
                          float* __restrict__ out) {
    int w = threadIdx.x >> 5, lane = threadIdx.x & 31;
    if (w < 10) {
        float s = 0.f;
        for (int k = lane; k < 512; k += 32) s += g_tap[k] * Wll[w * 512 + k];
#pragma unroll
        for (int off = 16; off; off >>= 1) s += __shfl_xor_sync(0xffffffffu, s, off);
        if (lane == 0) out[w] = s + bll[w];
    }
}

// ---------------- host ----------------
extern "C" void kernel_launch(void* const* d_in, const int* in_sizes, int n_in,
                              void* d_out, int out_size) {
    const float* x   = (const float*)d_in[0];
    const int*   ei  = (const int*)d_in[1];
    const float* W1_0 = (const float*)d_in[2];
    const float* b1_0 = (const float*)d_in[3];
    const float* g0   = (const float*)d_in[4];
    const float* be0  = (const float*)d_in[5];
    const float* m0   = (const float*)d_in[6];
    const float* v0   = (const float*)d_in[7];
    const float* W2_0 = (const float*)d_in[8];
    const float* b2_0 = (const float*)d_in[9];
    const float* W1s  = (const float*)d_in[10];
    const float* b1s  = (const float*)d_in[11];
    const float* gs   = (const float*)d_in[12];
    const float* bes  = (const float*)d_in[13];
    const float* ms   = (const float*)d_in[14];
    const float* vs   = (const float*)d_in[15];
    const float* W2s  = (const float*)d_in[16];
    const float* b2s  = (const float*)d_in[17];
    const float* Wll  = (const float*)d_in[18];
    const float* bll  = (const float*)d_in[19];
    float* out = (float*)d_out;

    cudaFuncSetAttribute(gin_layer, cudaFuncAttributeMaxDynamicSharedMemorySize, SMEM_BYTES);

    const int* esrc_in = ei;        // edge_index[0] = src
    const int* edst_in = ei + NE;   // edge_index[1] = dst

    zero_k<<<(NN + 255) / 256, 256>>>();
    hist_k<<<(NE + 255) / 256, 256>>>(edst_in);
    scan_k<<<1, 1024>>>();
    scatter_k<<<(NE + 255) / 256, 256>>>(esrc_in, edst_in);

    // layer 0: x -> g_x1
    gin_layer<<<NB, 512, SMEM_BYTES>>>(x, 0, 1, 0,
                                       W1_0, b1_0, g0, be0, m0, v0, W2_0, b2_0);
    // layers 1..3 ping-pong g_x1 <-> g_x2
    for (int i = 1; i < 4; i++) {
        int in_sel = (i % 2 == 1) ? 1 : 2;
        int out_sel = (i % 2 == 1) ? 2 : 1;
        int off = i - 1;
        gin_layer<<<NB, 512, SMEM_BYTES>>>(nullptr, in_sel, out_sel, i * 128,
                                           W1s + off * 16384, b1s + off * 128,
                                           gs + off * 128, bes + off * 128,
                                           ms + off * 128, vs + off * 128,
                                           W2s + off * 16384, b2s + off * 128);
    }
    readout_k<<<1, 320>>>(Wll, bll, out);
}

// round 2
// speedup vs baseline: 1.1870x; 1.1870x over previous
#include <cuda_runtime.h>
#include <cuda_bf16.h>
#include <cstdint>

#define NN 50000
#define NE 600000
#define HIDD 128
#define AS 132                       // padded row stride (floats): conflict-free, float4-aligned
#define SMEM_WORDS (2*128*AS + 4*128)
#define SMEM_BYTES (SMEM_WORDS*4)
#define NB ((NN + 127) / 128)
#define NSB ((NN + 255) / 256)       // scan blocks (196)

// ---------------- device scratch (static, no runtime alloc) ----------------
__device__ __align__(16) float g_x1[(size_t)NN * HIDD];
__device__ __align__(16) float g_x2[(size_t)NN * HIDD];
__device__ __align__(16) float g_agg[(size_t)NN * HIDD];
__device__ int   g_deg[NN];
__device__ int   g_rowptr[NN + 1];
__device__ int   g_cursor[NN];
__device__ int   g_esrc[NE];
__device__ int   g_bsum[256];
__device__ int   g_boff[256];
__device__ float g_tap[4 * HIDD];

// ---------------- helpers ----------------
__device__ __forceinline__ unsigned f2t(float f) {
    unsigned u;
    asm("cvt.rna.tf32.f32 %0, %1;" : "=r"(u) : "f"(f));
    return u;
}

__device__ __forceinline__ void mma8(float c[4], unsigned a0, unsigned a1, unsigned a2,
                                     unsigned a3, unsigned b0, unsigned b1) {
    asm volatile(
        "mma.sync.aligned.m16n8k8.row.col.f32.tf32.tf32.f32 "
        "{%0,%1,%2,%3},{%4,%5,%6,%7},{%8,%9},{%0,%1,%2,%3};"
        : "+f"(c[0]), "+f"(c[1]), "+f"(c[2]), "+f"(c[3])
        : "r"(a0), "r"(a1), "r"(a2), "r"(a3), "r"(b0), "r"(b1));
}

// ---------------- CSR build ----------------
__global__ void zero_k() {
    int i = blockIdx.x * blockDim.x + threadIdx.x;
    if (i < NN) g_deg[i] = 0;
    if (i < 4 * HIDD) g_tap[i] = 0.f;
}

__global__ void hist_k(const int* __restrict__ dst) {
    int i = blockIdx.x * blockDim.x + threadIdx.x;
    if (i < NE) atomicAdd(&g_deg[dst[i]], 1);
}

// coalesced block-sum of degrees
__global__ void part_k() {
    __shared__ int red[8];
    int i = blockIdx.x * 256 + threadIdx.x;
    int v = (i < NN) ? g_deg[i] : 0;
#pragma unroll
    for (int off = 16; off; off >>= 1) v += __shfl_xor_sync(0xffffffffu, v, off);
    if ((threadIdx.x & 31) == 0) red[threadIdx.x >> 5] = v;
    __syncthreads();
    if (threadIdx.x == 0) {
        int s = 0;
#pragma unroll
        for (int j = 0; j < 8; j++) s += red[j];
        g_bsum[blockIdx.x] = s;
    }
}

// exclusive scan of the 196 block sums (1 block)
__global__ void off_k() {
    __shared__ int sh[256];
    int t = threadIdx.x;
    sh[t] = (t < NSB) ? g_bsum[t] : 0;
    __syncthreads();
    for (int off = 1; off < 256; off <<= 1) {
        int v = (t >= off) ? sh[t - off] : 0;
        __syncthreads();
        sh[t] += v;
        __syncthreads();
    }
    g_boff[t] = (t == 0) ? 0 : sh[t - 1];
}

// final rowptr: block-local inclusive scan + block offset
__global__ void rowptr_k() {
    __shared__ int sh[256];
    int t = threadIdx.x;
    int i = blockIdx.x * 256 + t;
    int d = (i < NN) ? g_deg[i] : 0;
    sh[t] = d;
    __syncthreads();
    for (int off = 1; off < 256; off <<= 1) {
        int v = (t >= off) ? sh[t - off] : 0;
        __syncthreads();
        sh[t] += v;
        __syncthreads();
    }
    if (i < NN) {
        int rp = g_boff[blockIdx.x] + sh[t] - d;  // exclusive
        g_rowptr[i] = rp;
        g_cursor[i] = rp;
    }
    if (i == NN - 1) g_rowptr[NN] = NE;
}

__global__ void scatter_k(const int* __restrict__ src, const int* __restrict__ dst) {
    int i = blockIdx.x * blockDim.x + threadIdx.x;
    if (i < NE) {
        int d = dst[i];
        int pos = atomicAdd(&g_cursor[d], 1);
        g_esrc[pos] = src[i];
    }
}

// ---------------- aggregation: warp per node, high occupancy ----------------
__global__ __launch_bounds__(256) void agg_k(const float* __restrict__ Xin) {
    int gw = (blockIdx.x * blockDim.x + threadIdx.x) >> 5;
    int lane = threadIdx.x & 31;
    if (gw >= NN) return;
    const float4* X4 = (const float4*)Xin;
    float4 acc = X4[(size_t)gw * 32 + lane];         // +x_i (eps=0 GIN)
    int e = g_rowptr[gw], e1 = g_rowptr[gw + 1];
    for (; e + 4 <= e1; e += 4) {
        int s0 = g_esrc[e], s1 = g_esrc[e + 1];
        int s2 = g_esrc[e + 2], s3 = g_esrc[e + 3];
        float4 v0 = X4[(size_t)s0 * 32 + lane];
        float4 v1 = X4[(size_t)s1 * 32 + lane];
        float4 v2 = X4[(size_t)s2 * 32 + lane];
        float4 v3 = X4[(size_t)s3 * 32 + lane];
        acc.x += v0.x + v1.x + v2.x + v3.x;
        acc.y += v0.y + v1.y + v2.y + v3.y;
        acc.z += v0.z + v1.z + v2.z + v3.z;
        acc.w += v0.w + v1.w + v2.w + v3.w;
    }
    for (; e < e1; e++) {
        float4 v = X4[(size_t)g_esrc[e] * 32 + lane];
        acc.x += v.x; acc.y += v.y; acc.z += v.z; acc.w += v.w;
    }
    ((float4*)g_agg)[(size_t)gw * 32 + lane] = acc;
}

// ---------------- fused GIN MLP layer (reads g_agg) ----------------
// 1024 threads, 32 warps; warp tile m16 x n32. Two back-to-back 128^3 GEMMs.
__global__ __launch_bounds__(1024, 1) void gin_layer(
    float* __restrict__ Xout, int tap_off,
    const float* __restrict__ W1, const float* __restrict__ b1,
    const float* __restrict__ gam, const float* __restrict__ bet,
    const float* __restrict__ mu, const float* __restrict__ var,
    const float* __restrict__ W2, const float* __restrict__ b2)
{
    extern __shared__ unsigned sm[];
    unsigned* sA = sm;                  // 128 x AS tf32 tile (A, then H1)
    unsigned* sW = sm + 128 * AS;       // 128 x AS tf32 weights (W1', then W2)
    float* sB1    = (float*)(sm + 2 * 128 * AS);
    float* sB2    = sB1 + 128;
    float* sTap   = sB2 + 128;
    float* sScale = sTap + 128;

    float* tap = g_tap + tap_off;

    const int tid = threadIdx.x;
    const int w = tid >> 5, lane = tid & 31;
    const int rowBase = blockIdx.x * 128;

    if (tid < 128) {
        sScale[tid] = gam[tid] * rsqrtf(var[tid] + 1e-5f);
        sTap[tid] = 0.f;
        sB2[tid] = b2[tid];
    }
    __syncthreads();

    // --- W1 with BN scale folded; A tile from g_agg ---
    for (int idx = tid; idx < 128 * 128; idx += 1024) {
        int c = idx >> 7, k = idx & 127;
        sW[c * AS + k] = f2t(W1[idx] * sScale[c]);
    }
    if (tid < 128)
        sB1[tid] = (b1[tid] - mu[tid]) * sScale[tid] + bet[tid];

    const float4* A4 = (const float4*)g_agg;
    for (int idx = tid; idx < 128 * 32; idx += 1024) {
        int r = idx >> 5, c4 = idx & 31;
        int n = rowBase + r;
        float4 v = make_float4(0.f, 0.f, 0.f, 0.f);
        if (n < NN) v = A4[(size_t)n * 32 + c4];
        uint4 u = make_uint4(f2t(v.x), f2t(v.y), f2t(v.z), f2t(v.w));
        *(uint4*)&sA[r * AS + c4 * 4] = u;
    }
    __syncthreads();

    // --- GEMM1: H1 = ReLU(A @ W1'^T + b1') ---
    const int wr = w & 7, wc = w >> 3;
    const int rb = wr * 16, cb = wc * 32;
    const int gq = lane >> 2, q = lane & 3;

    float acc1[4][4];
#pragma unroll
    for (int nt = 0; nt < 4; nt++)
#pragma unroll
        for (int j = 0; j < 4; j++) acc1[nt][j] = 0.f;

#pragma unroll
    for (int kt = 0; kt < 16; kt++) {
        int k0 = kt * 8 + q;
        unsigned a0 = sA[(rb + gq) * AS + k0];
        unsigned a1 = sA[(rb + gq + 8) * AS + k0];
        unsigned a2 = sA[(rb + gq) * AS + k0 + 4];
        unsigned a3 = sA[(rb + gq + 8) * AS + k0 + 4];
#pragma unroll
        for (int nt = 0; nt < 4; nt++) {
            int n0 = cb + nt * 8 + gq;
            unsigned b0 = sW[n0 * AS + k0];
            unsigned b1v = sW[n0 * AS + k0 + 4];
            mma8(acc1[nt], a0, a1, a2, a3, b0, b1v);
        }
    }
    __syncthreads();

    // --- H1 -> sA (tf32), W2 -> sW ---
#pragma unroll
    for (int nt = 0; nt < 4; nt++) {
        int c0 = cb + nt * 8 + q * 2;
        float o00 = fmaxf(acc1[nt][0] + sB1[c0], 0.f);
        float o01 = fmaxf(acc1[nt][1] + sB1[c0 + 1], 0.f);
        float o10 = fmaxf(acc1[nt][2] + sB1[c0], 0.f);
        float o11 = fmaxf(acc1[nt][3] + sB1[c0 + 1], 0.f);
        uint2 u0 = make_uint2(f2t(o00), f2t(o01));
        uint2 u1 = make_uint2(f2t(o10), f2t(o11));
        *(uint2*)&sA[(rb + gq) * AS + c0] = u0;
        *(uint2*)&sA[(rb + gq + 8) * AS + c0] = u1;
    }
    for (int idx = tid; idx < 128 * 128; idx += 1024) {
        int c = idx >> 7, k = idx & 127;
        sW[c * AS + k] = f2t(W2[idx]);
    }
    __syncthreads();

    // --- GEMM2: H2 = ReLU(H1 @ W2^T + b2) ---
    float acc2[4][4];
#pragma unroll
    for (int nt = 0; nt < 4; nt++)
#pragma unroll
        for (int j = 0; j < 4; j++) acc2[nt][j] = 0.f;

#pragma unroll
    for (int kt = 0; kt < 16; kt++) {
        int k0 = kt * 8 + q;
        unsigned a0 = sA[(rb + gq) * AS + k0];
        unsigned a1 = sA[(rb + gq + 8) * AS + k0];
        unsigned a2 = sA[(rb + gq) * AS + k0 + 4];
        unsigned a3 = sA[(rb + gq + 8) * AS + k0 + 4];
#pragma unroll
        for (int nt = 0; nt < 4; nt++) {
            int n0 = cb + nt * 8 + gq;
            unsigned b0 = sW[n0 * AS + k0];
            unsigned b1v = sW[n0 * AS + k0 + 4];
            mma8(acc2[nt], a0, a1, a2, a3, b0, b1v);
        }
    }

    // --- epilogue: write Xout, accumulate per-layer tap column sums ---
    const int r0 = rowBase + rb + gq;
    const int r1 = r0 + 8;
    const bool m0v = (r0 < NN), m1v = (r1 < NN);
#pragma unroll
    for (int nt = 0; nt < 4; nt++) {
        int c0 = cb + nt * 8 + q * 2;
        float o00 = m0v ? fmaxf(acc2[nt][0] + sB2[c0], 0.f) : 0.f;
        float o01 = m0v ? fmaxf(acc2[nt][1] + sB2[c0 + 1], 0.f) : 0.f;
        float o10 = m1v ? fmaxf(acc2[nt][2] + sB2[c0], 0.f) : 0.f;
        float o11 = m1v ? fmaxf(acc2[nt][3] + sB2[c0 + 1], 0.f) : 0.f;
        if (m0v) *(float2*)&Xout[(size_t)r0 * 128 + c0] = make_float2(o00, o01);
        if (m1v) *(float2*)&Xout[(size_t)r1 * 128 + c0] = make_float2(o10, o11);
        atomicAdd(&sTap[c0], o00 + o10);
        atomicAdd(&sTap[c0 + 1], o01 + o11);
    }
    __syncthreads();
    if (tid < 128) atomicAdd(&tap[tid], sTap[tid]);
}

// ---------------- readout ----------------
__global__ void readout_k(const float* __restrict__ Wll, const float* __restrict__ bll,
                          float* __restrict__ out) {
    int w = threadIdx.x >> 5, lane = threadIdx.x & 31;
    if (w < 10) {
        float s = 0.f;
        for (int k = lane; k < 512; k += 32) s += g_tap[k] * Wll[w * 512 + k];
#pragma unroll
        for (int off = 16; off; off >>= 1) s += __shfl_xor_sync(0xffffffffu, s, off);
        if (lane == 0) out[w] = s + bll[w];
    }
}

// ---------------- host ----------------
extern "C" void kernel_launch(void* const* d_in, const int* in_sizes, int n_in,
                              void* d_out, int out_size) {
    const float* x   = (const float*)d_in[0];
    const int*   ei  = (const int*)d_in[1];
    const float* W1_0 = (const float*)d_in[2];
    const float* b1_0 = (const float*)d_in[3];
    const float* g0   = (const float*)d_in[4];
    const float* be0  = (const float*)d_in[5];
    const float* m0   = (const float*)d_in[6];
    const float* v0   = (const float*)d_in[7];
    const float* W2_0 = (const float*)d_in[8];
    const float* b2_0 = (const float*)d_in[9];
    const float* W1s  = (const float*)d_in[10];
    const float* b1s  = (const float*)d_in[11];
    const float* gs   = (const float*)d_in[12];
    const float* bes  = (const float*)d_in[13];
    const float* ms   = (const float*)d_in[14];
    const float* vs   = (const float*)d_in[15];
    const float* W2s  = (const float*)d_in[16];
    const float* b2s  = (const float*)d_in[17];
    const float* Wll  = (const float*)d_in[18];
    const float* bll  = (const float*)d_in[19];
    float* out = (float*)d_out;

    cudaFuncSetAttribute(gin_layer, cudaFuncAttributeMaxDynamicSharedMemorySize, SMEM_BYTES);

    const int* esrc_in = ei;        // edge_index[0] = src
    const int* edst_in = ei + NE;   // edge_index[1] = dst

    // CSR build
    zero_k<<<(NN + 255) / 256, 256>>>();
    hist_k<<<(NE + 255) / 256, 256>>>(edst_in);
    part_k<<<NSB, 256>>>();
    off_k<<<1, 256>>>();
    rowptr_k<<<NSB, 256>>>();
    scatter_k<<<(NE + 255) / 256, 256>>>(esrc_in, edst_in);

    // resolve ping-pong buffers via device symbol addresses is not needed:
    // layer 0: agg(x) -> gin -> g_x1 ; layers 1..3 ping-pong g_x1 <-> g_x2
    float* dx1; cudaGetSymbolAddress((void**)&dx1, g_x1);
    float* dx2; cudaGetSymbolAddress((void**)&dx2, g_x2);

    const int aggGrid = (NN * 32 + 255) / 256;

    agg_k<<<aggGrid, 256>>>(x);
    gin_layer<<<NB, 1024, SMEM_BYTES>>>(dx1, 0,
                                        W1_0, b1_0, g0, be0, m0, v0, W2_0, b2_0);
    for (int i = 1; i < 4; i++) {
        const float* Xin = (i % 2 == 1) ? dx1 : dx2;
        float* Xo = (i % 2 == 1) ? dx2 : dx1;
        int off = i - 1;
        agg_k<<<aggGrid, 256>>>(Xin);
        gin_layer<<<NB, 1024, SMEM_BYTES>>>(Xo, i * 128,
                                            W1s + off * 16384, b1s + off * 128,
                                            gs + off * 128, bes + off * 128,
                                            ms + off * 128, vs + off * 128,
                                            W2s + off * 16384, b2s + off * 128);
    }
    readout_k<<<1, 320>>>(Wll, bll, out);
}

// round 3
// speedup vs baseline: 1.7496x; 1.4740x over previous
#include <cuda_runtime.h>
#include <cuda_bf16.h>
#include <cstdint>

#define NN 50000
#define NE 600000
#define HIDD 128
#define AS 132                       // padded row stride (floats): conflict-free, float4-aligned
#define SMEM_WORDS (2*128*AS + 4*128)
#define SMEM_BYTES (SMEM_WORDS*4)
#define NB ((NN + 127) / 128)
#define NSB ((NN + 255) / 256)       // scan blocks (196)

#define ST_AGG (1 << 30)
#define ST_INC (2 << 30)
#define VALMASK 0x3FFFFFFF

// ---------------- device scratch (static, no runtime alloc) ----------------
__device__ __align__(16) float g_x1[(size_t)NN * HIDD];
__device__ __align__(16) float g_x2[(size_t)NN * HIDD];
__device__ __align__(16) float g_agg[(size_t)NN * HIDD];
__device__ int   g_deg[NN];
__device__ int   g_rowptr[NN + 1];
__device__ int   g_cursor[NN];
__device__ int   g_esrc[NE];
__device__ int   g_lb[NSB];
__device__ float g_tap[4 * HIDD];

// ---------------- helpers ----------------
__device__ __forceinline__ unsigned f2t(float f) {
    unsigned u;
    asm("cvt.rna.tf32.f32 %0, %1;" : "=r"(u) : "f"(f));
    return u;
}

__device__ __forceinline__ void mma8(float c[4], unsigned a0, unsigned a1, unsigned a2,
                                     unsigned a3, unsigned b0, unsigned b1) {
    asm volatile(
        "mma.sync.aligned.m16n8k8.row.col.f32.tf32.tf32.f32 "
        "{%0,%1,%2,%3},{%4,%5,%6,%7},{%8,%9},{%0,%1,%2,%3};"
        : "+f"(c[0]), "+f"(c[1]), "+f"(c[2]), "+f"(c[3])
        : "r"(a0), "r"(a1), "r"(a2), "r"(a3), "r"(b0), "r"(b1));
}

// ---------------- CSR build ----------------
// hist also zeroes lookback state + taps (read only by later kernels)
__global__ void hist_k(const int* __restrict__ dst) {
    int i = blockIdx.x * blockDim.x + threadIdx.x;
    if (i < NSB) g_lb[i] = 0;
    if (i < 4 * HIDD) g_tap[i] = 0.f;
    if (i < NE) atomicAdd(&g_deg[dst[i]], 1);
}

// single-kernel exclusive scan of g_deg via decoupled lookback
__global__ __launch_bounds__(256) void scan_lb_k() {
    __shared__ int warpsum[8];
    __shared__ int s_prefix;
    const int b = blockIdx.x, t = threadIdx.x;
    const int lane = t & 31, wid = t >> 5;
    const int i = b * 256 + t;
    int d = (i < NN) ? g_deg[i] : 0;

    // inclusive scan within warp
    int v = d;
#pragma unroll
    for (int o = 1; o < 32; o <<= 1) {
        int u = __shfl_up_sync(0xffffffffu, v, o);
        if (lane >= o) v += u;
    }
    if (lane == 31) warpsum[wid] = v;
    __syncthreads();
    if (t < 8) {
        int wv = warpsum[t];
#pragma unroll
        for (int o = 1; o < 8; o <<= 1) {
            int u = __shfl_up_sync(0xffu, wv, o);
            if (t >= o) wv += u;
        }
        warpsum[t] = wv;
    }
    __syncthreads();
    const int incl = v + (wid ? warpsum[wid - 1] : 0);
    const int total = warpsum[7];

    if (t == 0) {
        if (b == 0) atomicExch(&g_lb[0], ST_INC | total);
        else        atomicExch(&g_lb[b], ST_AGG | total);
    }

    if (wid == 0) {
        int prefix = 0;
        if (b > 0) {
            int idx = b - 1;
            while (true) {
                int j = idx - lane;
                int w = (j >= 0) ? atomicAdd(&g_lb[j], 0) : (ST_INC | 0);
                if (!__all_sync(0xffffffffu, w != 0)) continue;   // someone not published yet
                unsigned incmask = __ballot_sync(0xffffffffu, (w & ST_INC) != 0);
                if (incmask) {
                    int first = __ffs(incmask) - 1;               // closest inclusive going back
                    int contrib = (lane <= first) ? (w & VALMASK) : 0;
#pragma unroll
                    for (int o = 16; o; o >>= 1) contrib += __shfl_xor_sync(0xffffffffu, contrib, o);
                    prefix += contrib;
                    break;
                } else {
                    int contrib = w & VALMASK;
#pragma unroll
                    for (int o = 16; o; o >>= 1) contrib += __shfl_xor_sync(0xffffffffu, contrib, o);
                    prefix += contrib;
                    idx -= 32;
                }
            }
            if (lane == 0) atomicExch(&g_lb[b], ST_INC | (prefix + total));
        }
        if (lane == 0) s_prefix = prefix;
    }
    __syncthreads();
    int rp = s_prefix + incl - d;   // exclusive prefix
    if (i < NN) { g_rowptr[i] = rp; g_cursor[i] = rp; }
    if (i == NN - 1) g_rowptr[NN] = NE;
}

__global__ void scatter_k(const int* __restrict__ src, const int* __restrict__ dst) {
    int i = blockIdx.x * blockDim.x + threadIdx.x;
    if (i < NE) {
        int d = dst[i];
        int pos = atomicAdd(&g_cursor[d], 1);
        g_esrc[pos] = src[i];
    }
}

// ---------------- aggregation: warp per node, high occupancy ----------------
__global__ __launch_bounds__(256) void agg_k(const float* __restrict__ Xin) {
    int gw = (blockIdx.x * blockDim.x + threadIdx.x) >> 5;
    int lane = threadIdx.x & 31;
    if (gw >= NN) return;
    const float4* X4 = (const float4*)Xin;
    float4 acc = X4[(size_t)gw * 32 + lane];         // +x_i (eps=0 GIN)
    int e = g_rowptr[gw], e1 = g_rowptr[gw + 1];
    for (; e + 4 <= e1; e += 4) {
        int s0 = g_esrc[e], s1 = g_esrc[e + 1];
        int s2 = g_esrc[e + 2], s3 = g_esrc[e + 3];
        float4 v0 = X4[(size_t)s0 * 32 + lane];
        float4 v1 = X4[(size_t)s1 * 32 + lane];
        float4 v2 = X4[(size_t)s2 * 32 + lane];
        float4 v3 = X4[(size_t)s3 * 32 + lane];
        acc.x += v0.x + v1.x + v2.x + v3.x;
        acc.y += v0.y + v1.y + v2.y + v3.y;
        acc.z += v0.z + v1.z + v2.z + v3.z;
        acc.w += v0.w + v1.w + v2.w + v3.w;
    }
    for (; e < e1; e++) {
        float4 v = X4[(size_t)g_esrc[e] * 32 + lane];
        acc.x += v.x; acc.y += v.y; acc.z += v.z; acc.w += v.w;
    }
    ((float4*)g_agg)[(size_t)gw * 32 + lane] = acc;
}

// ---------------- fused GIN MLP layer (reads g_agg) ----------------
// 512 threads, 16 warps, warp tile m32 x n32. Two back-to-back 128^3 GEMMs.
__global__ __launch_bounds__(512, 1) void gin_layer(
    float* __restrict__ Xout, int tap_off,
    const float* __restrict__ W1, const float* __restrict__ b1,
    const float* __restrict__ gam, const float* __restrict__ bet,
    const float* __restrict__ mu, const float* __restrict__ var,
    const float* __restrict__ W2, const float* __restrict__ b2)
{
    extern __shared__ unsigned sm[];
    unsigned* sA = sm;                  // 128 x AS tf32 tile (A, then H1)
    unsigned* sW = sm + 128 * AS;       // 128 x AS tf32 weights (W1', then W2)
    float* sB1    = (float*)(sm + 2 * 128 * AS);
    float* sB2    = sB1 + 128;
    float* sTap   = sB2 + 128;
    float* sScale = sTap + 128;

    float* tap = g_tap + tap_off;

    const int tid = threadIdx.x;
    const int w = tid >> 5, lane = tid & 31;
    const int rowBase = blockIdx.x * 128;

    if (tid < 128) {
        sScale[tid] = gam[tid] * rsqrtf(var[tid] + 1e-5f);
        sTap[tid] = 0.f;
        sB2[tid] = b2[tid];
        sB1[tid] = 0.f;   // placeholder; real value set below after sScale visible
    }
    __syncthreads();

    // --- W1 (BN folded, float4 loads) + b1' ---
    const float4* W14 = (const float4*)W1;
    for (int idx = tid; idx < 4096; idx += 512) {
        int c = idx >> 5, k4 = (idx & 31) * 4;
        float4 v = W14[idx];
        float s = sScale[c];
        uint4 u = make_uint4(f2t(v.x * s), f2t(v.y * s), f2t(v.z * s), f2t(v.w * s));
        *(uint4*)&sW[c * AS + k4] = u;
    }
    if (tid < 128)
        sB1[tid] = (b1[tid] - mu[tid]) * sScale[tid] + bet[tid];

    // --- A tile from g_agg (float4) ---
    const float4* A4 = (const float4*)g_agg;
    for (int idx = tid; idx < 4096; idx += 512) {
        int r = idx >> 5, c4 = idx & 31;
        int n = rowBase + r;
        float4 v = make_float4(0.f, 0.f, 0.f, 0.f);
        if (n < NN) v = A4[(size_t)n * 32 + c4];
        uint4 u = make_uint4(f2t(v.x), f2t(v.y), f2t(v.z), f2t(v.w));
        *(uint4*)&sA[r * AS + c4 * 4] = u;
    }
    __syncthreads();

    // warp tiling: 16 warps = 4 row-tiles x 4 col-strips
    const int wr = w & 3, wc = w >> 2;
    const int rb = wr * 32, cb = wc * 32;
    const int gq = lane >> 2, q = lane & 3;

    // --- GEMM1: H1 = ReLU(A @ W1'^T + b1') ---
    float acc1[2][4][4];
#pragma unroll
    for (int rt = 0; rt < 2; rt++)
#pragma unroll
        for (int nt = 0; nt < 4; nt++)
#pragma unroll
            for (int j = 0; j < 4; j++) acc1[rt][nt][j] = 0.f;

#pragma unroll
    for (int kt = 0; kt < 16; kt++) {
        int k0 = kt * 8 + q;
        unsigned a00 = sA[(rb + gq) * AS + k0];
        unsigned a01 = sA[(rb + gq) * AS + k0 + 4];
        unsigned a10 = sA[(rb + 8 + gq) * AS + k0];
        unsigned a11 = sA[(rb + 8 + gq) * AS + k0 + 4];
        unsigned a20 = sA[(rb + 16 + gq) * AS + k0];
        unsigned a21 = sA[(rb + 16 + gq) * AS + k0 + 4];
        unsigned a30 = sA[(rb + 24 + gq) * AS + k0];
        unsigned a31 = sA[(rb + 24 + gq) * AS + k0 + 4];
#pragma unroll
        for (int nt = 0; nt < 4; nt++) {
            int n0 = cb + nt * 8 + gq;
            unsigned b0 = sW[n0 * AS + k0];
            unsigned b1v = sW[n0 * AS + k0 + 4];
            mma8(acc1[0][nt], a00, a10, a01, a11, b0, b1v);
            mma8(acc1[1][nt], a20, a30, a21, a31, b0, b1v);
        }
    }
    __syncthreads();

    // --- H1 -> sA (tf32), W2 -> sW ---
#pragma unroll
    for (int rt = 0; rt < 2; rt++) {
        int r0 = rb + 16 * rt + gq;
#pragma unroll
        for (int nt = 0; nt < 4; nt++) {
            int c0 = cb + nt * 8 + q * 2;
            float o00 = fmaxf(acc1[rt][nt][0] + sB1[c0], 0.f);
            float o01 = fmaxf(acc1[rt][nt][1] + sB1[c0 + 1], 0.f);
            float o10 = fmaxf(acc1[rt][nt][2] + sB1[c0], 0.f);
            float o11 = fmaxf(acc1[rt][nt][3] + sB1[c0 + 1], 0.f);
            *(uint2*)&sA[r0 * AS + c0] = make_uint2(f2t(o00), f2t(o01));
            *(uint2*)&sA[(r0 + 8) * AS + c0] = make_uint2(f2t(o10), f2t(o11));
        }
    }
    const float4* W24 = (const float4*)W2;
    for (int idx = tid; idx < 4096; idx += 512) {
        int c = idx >> 5, k4 = (idx & 31) * 4;
        float4 v = W24[idx];
        uint4 u = make_uint4(f2t(v.x), f2t(v.y), f2t(v.z), f2t(v.w));
        *(uint4*)&sW[c * AS + k4] = u;
    }
    __syncthreads();

    // --- GEMM2: H2 = ReLU(H1 @ W2^T + b2) ---
    float acc2[2][4][4];
#pragma unroll
    for (int rt = 0; rt < 2; rt++)
#pragma unroll
        for (int nt = 0; nt < 4; nt++)
#pragma unroll
            for (int j = 0; j < 4; j++) acc2[rt][nt][j] = 0.f;

#pragma unroll
    for (int kt = 0; kt < 16; kt++) {
        int k0 = kt * 8 + q;
        unsigned a00 = sA[(rb + gq) * AS + k0];
        unsigned a01 = sA[(rb + gq) * AS + k0 + 4];
        unsigned a10 = sA[(rb + 8 + gq) * AS + k0];
        unsigned a11 = sA[(rb + 8 + gq) * AS + k0 + 4];
        unsigned a20 = sA[(rb + 16 + gq) * AS + k0];
        unsigned a21 = sA[(rb + 16 + gq) * AS + k0 + 4];
        unsigned a30 = sA[(rb + 24 + gq) * AS + k0];
        unsigned a31 = sA[(rb + 24 + gq) * AS + k0 + 4];
#pragma unroll
        for (int nt = 0; nt < 4; nt++) {
            int n0 = cb + nt * 8 + gq;
            unsigned b0 = sW[n0 * AS + k0];
            unsigned b1v = sW[n0 * AS + k0 + 4];
            mma8(acc2[0][nt], a00, a10, a01, a11, b0, b1v);
            mma8(acc2[1][nt], a20, a30, a21, a31, b0, b1v);
        }
    }

    // --- epilogue: write Xout, tap column sums (shuffle-reduced) ---
    float tS0[4], tS1[4];
#pragma unroll
    for (int nt = 0; nt < 4; nt++) { tS0[nt] = 0.f; tS1[nt] = 0.f; }

#pragma unroll
    for (int rt = 0; rt < 2; rt++) {
        int r0 = rowBase + rb + 16 * rt + gq;
        int r1 = r0 + 8;
        bool m0v = (r0 < NN), m1v = (r1 < NN);
#pragma unroll
        for (int nt = 0; nt < 4; nt++) {
            int c0 = cb + nt * 8 + q * 2;
            float o00 = m0v ? fmaxf(acc2[rt][nt][0] + sB2[c0], 0.f) : 0.f;
            float o01 = m0v ? fmaxf(acc2[rt][nt][1] + sB2[c0 + 1], 0.f) : 0.f;
            float o10 = m1v ? fmaxf(acc2[rt][nt][2] + sB2[c0], 0.f) : 0.f;
            float o11 = m1v ? fmaxf(acc2[rt][nt][3] + sB2[c0 + 1], 0.f) : 0.f;
            if (m0v) *(float2*)&Xout[(size_t)r0 * 128 + c0] = make_float2(o00, o01);
            if (m1v) *(float2*)&Xout[(size_t)r1 * 128 + c0] = make_float2(o10, o11);
            tS0[nt] += o00 + o10;
            tS1[nt] += o01 + o11;
        }
    }
    // reduce across gq lanes (stride-4 lane groups), then 4 lanes do atomics
#pragma unroll
    for (int nt = 0; nt < 4; nt++) {
        float t0 = tS0[nt], t1 = tS1[nt];
#pragma unroll
        for (int o = 16; o >= 4; o >>= 1) {
            t0 += __shfl_xor_sync(0xffffffffu, t0, o);
            t1 += __shfl_xor_sync(0xffffffffu, t1, o);
        }
        if (gq == 0) {
            int c0 = cb + nt * 8 + q * 2;
            atomicAdd(&sTap[c0], t0);
            atomicAdd(&sTap[c0 + 1], t1);
        }
    }
    __syncthreads();
    if (tid < 128) atomicAdd(&tap[tid], sTap[tid]);
}

// ---------------- readout ----------------
__global__ void readout_k(const float* __restrict__ Wll, const float* __restrict__ bll,
                          float* __restrict__ out) {
    int w = threadIdx.x >> 5, lane = threadIdx.x & 31;
    if (w < 10) {
        float s = 0.f;
        for (int k = lane; k < 512; k += 32) s += g_tap[k] * Wll[w * 512 + k];
#pragma unroll
        for (int off = 16; off; off >>= 1) s += __shfl_xor_sync(0xffffffffu, s, off);
        if (lane == 0) out[w] = s + bll[w];
    }
}

// ---------------- host ----------------
extern "C" void kernel_launch(void* const* d_in, const int* in_sizes, int n_in,
                              void* d_out, int out_size) {
    const float* x   = (const float*)d_in[0];
    const int*   ei  = (const int*)d_in[1];
    const float* W1_0 = (const float*)d_in[2];
    const float* b1_0 = (const float*)d_in[3];
    const float* g0   = (const float*)d_in[4];
    const float* be0  = (const float*)d_in[5];
    const float* m0   = (const float*)d_in[6];
    const float* v0   = (const float*)d_in[7];
    const float* W2_0 = (const float*)d_in[8];
    const float* b2_0 = (const float*)d_in[9];
    const float* W1s  = (const float*)d_in[10];
    const float* b1s  = (const float*)d_in[11];
    const float* gs   = (const float*)d_in[12];
    const float* bes  = (const float*)d_in[13];
    const float* ms   = (const float*)d_in[14];
    const float* vs   = (const float*)d_in[15];
    const float* W2s  = (const float*)d_in[16];
    const float* b2s  = (const float*)d_in[17];
    const float* Wll  = (const float*)d_in[18];
    const float* bll  = (const float*)d_in[19];
    float* out = (float*)d_out;

    cudaFuncSetAttribute(gin_layer, cudaFuncAttributeMaxDynamicSharedMemorySize, SMEM_BYTES);

    const int* esrc_in = ei;        // edge_index[0] = src
    const int* edst_in = ei + NE;   // edge_index[1] = dst

    // zero degree array via memset node (not a kernel launch)
    void* dDeg; cudaGetSymbolAddress(&dDeg, g_deg);
    cudaMemsetAsync(dDeg, 0, NN * sizeof(int), 0);

    // CSR build: 3 kernel launches
    hist_k<<<(NE + 255) / 256, 256>>>(edst_in);
    scan_lb_k<<<NSB, 256>>>();
    scatter_k<<<(NE + 255) / 256, 256>>>(esrc_in, edst_in);

    float* dx1; cudaGetSymbolAddress((void**)&dx1, g_x1);
    float* dx2; cudaGetSymbolAddress((void**)&dx2, g_x2);

    const int aggGrid = (NN * 32 + 255) / 256;

    // launch #4 = agg_k (gets profiled by ncu)
    agg_k<<<aggGrid, 256>>>(x);
    gin_layer<<<NB, 512, SMEM_BYTES>>>(dx1, 0,
                                       W1_0, b1_0, g0, be0, m0, v0, W2_0, b2_0);
    for (int i = 1; i < 4; i++) {
        const float* Xin = (i % 2 == 1) ? dx1 : dx2;
        float* Xo = (i % 2 == 1) ? dx2 : dx1;
        int off = i - 1;
        agg_k<<<aggGrid, 256>>>(Xin);
        gin_layer<<<NB, 512, SMEM_BYTES>>>(Xo, i * 128,
                                           W1s + off * 16384, b1s + off * 128,
                                           gs + off * 128, bes + off * 128,
                                           ms + off * 128, vs + off * 128,
                                           W2s + off * 16384, b2s + off * 128);
    }
    readout_k<<<1, 320>>>(Wll, bll, out);
}

// round 4
// speedup vs baseline: 2.1565x; 1.2326x over previous
#include <cuda_runtime.h>
#include <cuda_bf16.h>
#include <cstdint>

#define NN 50000
#define NE 600000
#define HIDD 128
#define AS 132                       // padded row stride (floats): conflict-free
#define SMEM_WORDS (3*128*AS + 4*128)
#define SMEM_BYTES (SMEM_WORDS*4)    // 204800 B
#define NB ((NN + 127) / 128)        // 391 tiles
#define NSB ((NN + 255) / 256)       // scan blocks (196)
#define PGRID 148                    // persistent grid

#define ST_AGG (1 << 30)
#define ST_INC (2 << 30)
#define VALMASK 0x3FFFFFFF

// ---------------- device scratch (static, no runtime alloc) ----------------
__device__ __align__(16) float g_x1[(size_t)NN * HIDD];
__device__ __align__(16) float g_x2[(size_t)NN * HIDD];
__device__ __align__(16) float g_agg[(size_t)NN * HIDD];
__device__ int   g_deg[NN];
__device__ int   g_rowptr[NN + 1];
__device__ int   g_cursor[NN];
__device__ int   g_esrc[NE];
__device__ int   g_lb[NSB];
__device__ float g_tap[4 * HIDD];

// ---------------- helpers ----------------
__device__ __forceinline__ unsigned f2t(float f) {
    unsigned u;
    asm("cvt.rna.tf32.f32 %0, %1;" : "=r"(u) : "f"(f));
    return u;
}

__device__ __forceinline__ void mma8(float c[4], unsigned a0, unsigned a1, unsigned a2,
                                     unsigned a3, unsigned b0, unsigned b1) {
    asm volatile(
        "mma.sync.aligned.m16n8k8.row.col.f32.tf32.tf32.f32 "
        "{%0,%1,%2,%3},{%4,%5,%6,%7},{%8,%9},{%0,%1,%2,%3};"
        : "+f"(c[0]), "+f"(c[1]), "+f"(c[2]), "+f"(c[3])
        : "r"(a0), "r"(a1), "r"(a2), "r"(a3), "r"(b0), "r"(b1));
}

// ---------------- CSR build ----------------
__global__ void hist_k(const int* __restrict__ dst) {
    int i = blockIdx.x * blockDim.x + threadIdx.x;
    if (i < NSB) g_lb[i] = 0;
    if (i < 4 * HIDD) g_tap[i] = 0.f;
    if (i < NE) atomicAdd(&g_deg[dst[i]], 1);
}

// single-kernel exclusive scan of g_deg via decoupled lookback
__global__ __launch_bounds__(256) void scan_lb_k() {
    __shared__ int warpsum[8];
    __shared__ int s_prefix;
    const int b = blockIdx.x, t = threadIdx.x;
    const int lane = t & 31, wid = t >> 5;
    const int i = b * 256 + t;
    int d = (i < NN) ? g_deg[i] : 0;

    int v = d;
#pragma unroll
    for (int o = 1; o < 32; o <<= 1) {
        int u = __shfl_up_sync(0xffffffffu, v, o);
        if (lane >= o) v += u;
    }
    if (lane == 31) warpsum[wid] = v;
    __syncthreads();
    if (t < 8) {
        int wv = warpsum[t];
#pragma unroll
        for (int o = 1; o < 8; o <<= 1) {
            int u = __shfl_up_sync(0xffu, wv, o);
            if (t >= o) wv += u;
        }
        warpsum[t] = wv;
    }
    __syncthreads();
    const int incl = v + (wid ? warpsum[wid - 1] : 0);
    const int total = warpsum[7];

    if (t == 0) {
        if (b == 0) atomicExch(&g_lb[0], ST_INC | total);
        else        atomicExch(&g_lb[b], ST_AGG | total);
    }

    if (wid == 0) {
        int prefix = 0;
        if (b > 0) {
            int idx = b - 1;
            while (true) {
                int j = idx - lane;
                int w = (j >= 0) ? atomicAdd(&g_lb[j], 0) : (ST_INC | 0);
                if (!__all_sync(0xffffffffu, w != 0)) continue;
                unsigned incmask = __ballot_sync(0xffffffffu, (w & ST_INC) != 0);
                if (incmask) {
                    int first = __ffs(incmask) - 1;
                    int contrib = (lane <= first) ? (w & VALMASK) : 0;
#pragma unroll
                    for (int o = 16; o; o >>= 1) contrib += __shfl_xor_sync(0xffffffffu, contrib, o);
                    prefix += contrib;
                    break;
                } else {
                    int contrib = w & VALMASK;
#pragma unroll
                    for (int o = 16; o; o >>= 1) contrib += __shfl_xor_sync(0xffffffffu, contrib, o);
                    prefix += contrib;
                    idx -= 32;
                }
            }
            if (lane == 0) atomicExch(&g_lb[b], ST_INC | (prefix + total));
        }
        if (lane == 0) s_prefix = prefix;
    }
    __syncthreads();
    int rp = s_prefix + incl - d;
    if (i < NN) { g_rowptr[i] = rp; g_cursor[i] = rp; }
    if (i == NN - 1) g_rowptr[NN] = NE;
}

__global__ void scatter_k(const int* __restrict__ src, const int* __restrict__ dst) {
    int i = blockIdx.x * blockDim.x + threadIdx.x;
    if (i < NE) {
        int d = dst[i];
        int pos = atomicAdd(&g_cursor[d], 1);
        g_esrc[pos] = src[i];
    }
}

// ---------------- aggregation: warp per node, high occupancy ----------------
__global__ __launch_bounds__(256) void agg_k(const float* __restrict__ Xin) {
    int gw = (blockIdx.x * blockDim.x + threadIdx.x) >> 5;
    int lane = threadIdx.x & 31;
    if (gw >= NN) return;
    const float4* X4 = (const float4*)Xin;
    float4 acc = X4[(size_t)gw * 32 + lane];         // +x_i (eps=0 GIN)
    int e = g_rowptr[gw], e1 = g_rowptr[gw + 1];
    for (; e + 8 <= e1; e += 8) {
        int s0 = g_esrc[e],     s1 = g_esrc[e + 1];
        int s2 = g_esrc[e + 2], s3 = g_esrc[e + 3];
        int s4 = g_esrc[e + 4], s5 = g_esrc[e + 5];
        int s6 = g_esrc[e + 6], s7 = g_esrc[e + 7];
        float4 v0 = X4[(size_t)s0 * 32 + lane];
        float4 v1 = X4[(size_t)s1 * 32 + lane];
        float4 v2 = X4[(size_t)s2 * 32 + lane];
        float4 v3 = X4[(size_t)s3 * 32 + lane];
        float4 v4 = X4[(size_t)s4 * 32 + lane];
        float4 v5 = X4[(size_t)s5 * 32 + lane];
        float4 v6 = X4[(size_t)s6 * 32 + lane];
        float4 v7 = X4[(size_t)s7 * 32 + lane];
        acc.x += ((v0.x + v1.x) + (v2.x + v3.x)) + ((v4.x + v5.x) + (v6.x + v7.x));
        acc.y += ((v0.y + v1.y) + (v2.y + v3.y)) + ((v4.y + v5.y) + (v6.y + v7.y));
        acc.z += ((v0.z + v1.z) + (v2.z + v3.z)) + ((v4.z + v5.z) + (v6.z + v7.z));
        acc.w += ((v0.w + v1.w) + (v2.w + v3.w)) + ((v4.w + v5.w) + (v6.w + v7.w));
    }
    for (; e + 4 <= e1; e += 4) {
        int s0 = g_esrc[e], s1 = g_esrc[e + 1];
        int s2 = g_esrc[e + 2], s3 = g_esrc[e + 3];
        float4 v0 = X4[(size_t)s0 * 32 + lane];
        float4 v1 = X4[(size_t)s1 * 32 + lane];
        float4 v2 = X4[(size_t)s2 * 32 + lane];
        float4 v3 = X4[(size_t)s3 * 32 + lane];
        acc.x += (v0.x + v1.x) + (v2.x + v3.x);
        acc.y += (v0.y + v1.y) + (v2.y + v3.y);
        acc.z += (v0.z + v1.z) + (v2.z + v3.z);
        acc.w += (v0.w + v1.w) + (v2.w + v3.w);
    }
    for (; e < e1; e++) {
        float4 v = X4[(size_t)g_esrc[e] * 32 + lane];
        acc.x += v.x; acc.y += v.y; acc.z += v.z; acc.w += v.w;
    }
    ((float4*)g_agg)[(size_t)gw * 32 + lane] = acc;
}

// ---------------- persistent fused GIN MLP layer (reads g_agg) ----------------
// 512 threads, 16 warps, warp tile m32 x n32. Weights resident in smem for the
// whole kernel; each block loops over row-tiles.
__global__ __launch_bounds__(512, 1) void gin_layer(
    float* __restrict__ Xout, int tap_off,
    const float* __restrict__ W1, const float* __restrict__ b1,
    const float* __restrict__ gam, const float* __restrict__ bet,
    const float* __restrict__ mu, const float* __restrict__ var,
    const float* __restrict__ W2, const float* __restrict__ b2)
{
    extern __shared__ unsigned sm[];
    unsigned* sW1 = sm;                    // 128 x AS tf32 (BN-folded W1)
    unsigned* sW2 = sm + 128 * AS;         // 128 x AS tf32 W2
    unsigned* sA  = sm + 2 * 128 * AS;     // 128 x AS tf32 tile (A, then H1)
    float* sB1    = (float*)(sm + 3 * 128 * AS);
    float* sB2    = sB1 + 128;
    float* sTap   = sB2 + 128;
    float* sScale = sTap + 128;

    float* tap = g_tap + tap_off;

    const int tid = threadIdx.x;
    const int w = tid >> 5, lane = tid & 31;

    if (tid < 128) {
        float sc = gam[tid] * rsqrtf(var[tid] + 1e-5f);
        sScale[tid] = sc;
        sTap[tid] = 0.f;
        sB2[tid] = b2[tid];
        sB1[tid] = (b1[tid] - mu[tid]) * sc + bet[tid];
    }
    __syncthreads();   // sScale visible for weight fold

    // --- load both weight matrices once (float4, f2t) ---
    const float4* W14 = (const float4*)W1;
    const float4* W24 = (const float4*)W2;
    for (int idx = tid; idx < 4096; idx += 512) {
        int c = idx >> 5, k4 = (idx & 31) * 4;
        float s = sScale[c];
        float4 v1 = W14[idx];
        *(uint4*)&sW1[c * AS + k4] =
            make_uint4(f2t(v1.x * s), f2t(v1.y * s), f2t(v1.z * s), f2t(v1.w * s));
        float4 v2 = W24[idx];
        *(uint4*)&sW2[c * AS + k4] =
            make_uint4(f2t(v2.x), f2t(v2.y), f2t(v2.z), f2t(v2.w));
    }
    // (first in-loop __syncthreads covers weight visibility)

    // warp tiling: 16 warps = 4 row-tiles x 4 col-strips
    const int wr = w & 3, wc = w >> 2;
    const int rb = wr * 32, cb = wc * 32;
    const int gq = lane >> 2, q = lane & 3;

    // per-thread tap accumulators across all tiles
    float tS0[4], tS1[4];
#pragma unroll
    for (int nt = 0; nt < 4; nt++) { tS0[nt] = 0.f; tS1[nt] = 0.f; }

    const float4* A4 = (const float4*)g_agg;

    for (int tile = blockIdx.x; tile < NB; tile += gridDim.x) {
        const int rowBase = tile * 128;

        // --- A tile from g_agg (float4) ---
        for (int idx = tid; idx < 4096; idx += 512) {
            int r = idx >> 5, c4 = idx & 31;
            int n = rowBase + r;
            float4 v = make_float4(0.f, 0.f, 0.f, 0.f);
            if (n < NN) v = A4[(size_t)n * 32 + c4];
            *(uint4*)&sA[r * AS + c4 * 4] =
                make_uint4(f2t(v.x), f2t(v.y), f2t(v.z), f2t(v.w));
        }
        __syncthreads();

        // --- GEMM1: H1 = ReLU(A @ W1'^T + b1') ---
        float acc1[2][4][4];
#pragma unroll
        for (int rt = 0; rt < 2; rt++)
#pragma unroll
            for (int nt = 0; nt < 4; nt++)
#pragma unroll
                for (int j = 0; j < 4; j++) acc1[rt][nt][j] = 0.f;

#pragma unroll
        for (int kt = 0; kt < 16; kt++) {
            int k0 = kt * 8 + q;
            unsigned a00 = sA[(rb + gq) * AS + k0];
            unsigned a01 = sA[(rb + gq) * AS + k0 + 4];
            unsigned a10 = sA[(rb + 8 + gq) * AS + k0];
            unsigned a11 = sA[(rb + 8 + gq) * AS + k0 + 4];
            unsigned a20 = sA[(rb + 16 + gq) * AS + k0];
            unsigned a21 = sA[(rb + 16 + gq) * AS + k0 + 4];
            unsigned a30 = sA[(rb + 24 + gq) * AS + k0];
            unsigned a31 = sA[(rb + 24 + gq) * AS + k0 + 4];
#pragma unroll
            for (int nt = 0; nt < 4; nt++) {
                int n0 = cb + nt * 8 + gq;
                unsigned b0 = sW1[n0 * AS + k0];
                unsigned b1v = sW1[n0 * AS + k0 + 4];
                mma8(acc1[0][nt], a00, a10, a01, a11, b0, b1v);
                mma8(acc1[1][nt], a20, a30, a21, a31, b0, b1v);
            }
        }
        __syncthreads();

        // --- H1 -> sA (tf32) ---
#pragma unroll
        for (int rt = 0; rt < 2; rt++) {
            int r0 = rb + 16 * rt + gq;
#pragma unroll
            for (int nt = 0; nt < 4; nt++) {
                int c0 = cb + nt * 8 + q * 2;
                float o00 = fmaxf(acc1[rt][nt][0] + sB1[c0], 0.f);
                float o01 = fmaxf(acc1[rt][nt][1] + sB1[c0 + 1], 0.f);
                float o10 = fmaxf(acc1[rt][nt][2] + sB1[c0], 0.f);
                float o11 = fmaxf(acc1[rt][nt][3] + sB1[c0 + 1], 0.f);
                *(uint2*)&sA[r0 * AS + c0] = make_uint2(f2t(o00), f2t(o01));
                *(uint2*)&sA[(r0 + 8) * AS + c0] = make_uint2(f2t(o10), f2t(o11));
            }
        }
        __syncthreads();

        // --- GEMM2: H2 = ReLU(H1 @ W2^T + b2) ---
        float acc2[2][4][4];
#pragma unroll
        for (int rt = 0; rt < 2; rt++)
#pragma unroll
            for (int nt = 0; nt < 4; nt++)
#pragma unroll
                for (int j = 0; j < 4; j++) acc2[rt][nt][j] = 0.f;

#pragma unroll
        for (int kt = 0; kt < 16; kt++) {
            int k0 = kt * 8 + q;
            unsigned a00 = sA[(rb + gq) * AS + k0];
            unsigned a01 = sA[(rb + gq) * AS + k0 + 4];
            unsigned a10 = sA[(rb + 8 + gq) * AS + k0];
            unsigned a11 = sA[(rb + 8 + gq) * AS + k0 + 4];
            unsigned a20 = sA[(rb + 16 + gq) * AS + k0];
            unsigned a21 = sA[(rb + 16 + gq) * AS + k0 + 4];
            unsigned a30 = sA[(rb + 24 + gq) * AS + k0];
            unsigned a31 = sA[(rb + 24 + gq) * AS + k0 + 4];
#pragma unroll
            for (int nt = 0; nt < 4; nt++) {
                int n0 = cb + nt * 8 + gq;
                unsigned b0 = sW2[n0 * AS + k0];
                unsigned b1v = sW2[n0 * AS + k0 + 4];
                mma8(acc2[0][nt], a00, a10, a01, a11, b0, b1v);
                mma8(acc2[1][nt], a20, a30, a21, a31, b0, b1v);
            }
        }

        // --- epilogue: write Xout, accumulate tap in regs ---
#pragma unroll
        for (int rt = 0; rt < 2; rt++) {
            int r0 = rowBase + rb + 16 * rt + gq;
            int r1 = r0 + 8;
            bool m0v = (r0 < NN), m1v = (r1 < NN);
#pragma unroll
            for (int nt = 0; nt < 4; nt++) {
                int c0 = cb + nt * 8 + q * 2;
                float o00 = m0v ? fmaxf(acc2[rt][nt][0] + sB2[c0], 0.f) : 0.f;
                float o01 = m0v ? fmaxf(acc2[rt][nt][1] + sB2[c0 + 1], 0.f) : 0.f;
                float o10 = m1v ? fmaxf(acc2[rt][nt][2] + sB2[c0], 0.f) : 0.f;
                float o11 = m1v ? fmaxf(acc2[rt][nt][3] + sB2[c0 + 1], 0.f) : 0.f;
                if (m0v) *(float2*)&Xout[(size_t)r0 * 128 + c0] = make_float2(o00, o01);
                if (m1v) *(float2*)&Xout[(size_t)r1 * 128 + c0] = make_float2(o10, o11);
                tS0[nt] += o00 + o10;
                tS1[nt] += o01 + o11;
            }
        }
        __syncthreads();   // sA reuse next tile
    }

    // --- final tap reduction: shuffle across gq lanes, then smem, then global ---
#pragma unroll
    for (int nt = 0; nt < 4; nt++) {
        float t0 = tS0[nt], t1 = tS1[nt];
#pragma unroll
        for (int o = 16; o >= 4; o >>= 1) {
            t0 += __shfl_xor_sync(0xffffffffu, t0, o);
            t1 += __shfl_xor_sync(0xffffffffu, t1, o);
        }
        if (gq == 0) {
            int c0 = cb + nt * 8 + q * 2;
            atomicAdd(&sTap[c0], t0);
            atomicAdd(&sTap[c0 + 1], t1);
        }
    }
    __syncthreads();
    if (tid < 128) atomicAdd(&tap[tid], sTap[tid]);
}

// ---------------- readout ----------------
__global__ void readout_k(const float* __restrict__ Wll, const float* __restrict__ bll,
                          float* __restrict__ out) {
    int w = threadIdx.x >> 5, lane = threadIdx.x & 31;
    if (w < 10) {
        float s = 0.f;
        for (int k = lane; k < 512; k += 32) s += g_tap[k] * Wll[w * 512 + k];
#pragma unroll
        for (int off = 16; off; off >>= 1) s += __shfl_xor_sync(0xffffffffu, s, off);
        if (lane == 0) out[w] = s + bll[w];
    }
}

// ---------------- host ----------------
extern "C" void kernel_launch(void* const* d_in, const int* in_sizes, int n_in,
                              void* d_out, int out_size) {
    const float* x   = (const float*)d_in[0];
    const int*   ei  = (const int*)d_in[1];
    const float* W1_0 = (const float*)d_in[2];
    const float* b1_0 = (const float*)d_in[3];
    const float* g0   = (const float*)d_in[4];
    const float* be0  = (const float*)d_in[5];
    const float* m0   = (const float*)d_in[6];
    const float* v0   = (const float*)d_in[7];
    const float* W2_0 = (const float*)d_in[8];
    const float* b2_0 = (const float*)d_in[9];
    const float* W1s  = (const float*)d_in[10];
    const float* b1s  = (const float*)d_in[11];
    const float* gs   = (const float*)d_in[12];
    const float* bes  = (const float*)d_in[13];
    const float* ms   = (const float*)d_in[14];
    const float* vs   = (const float*)d_in[15];
    const float* W2s  = (const float*)d_in[16];
    const float* b2s  = (const float*)d_in[17];
    const float* Wll  = (const float*)d_in[18];
    const float* bll  = (const float*)d_in[19];
    float* out = (float*)d_out;

    cudaFuncSetAttribute(gin_layer, cudaFuncAttributeMaxDynamicSharedMemorySize, SMEM_BYTES);

    const int* esrc_in = ei;        // edge_index[0] = src
    const int* edst_in = ei + NE;   // edge_index[1] = dst

    void* dDeg; cudaGetSymbolAddress(&dDeg, g_deg);
    cudaMemsetAsync(dDeg, 0, NN * sizeof(int), 0);

    hist_k<<<(NE + 255) / 256, 256>>>(edst_in);
    scan_lb_k<<<NSB, 256>>>();
    scatter_k<<<(NE + 255) / 256, 256>>>(esrc_in, edst_in);

    float* dx1; cudaGetSymbolAddress((void**)&dx1, g_x1);
    float* dx2; cudaGetSymbolAddress((void**)&dx2, g_x2);

    const int aggGrid = (NN * 32 + 255) / 256;

    agg_k<<<aggGrid, 256>>>(x);
    gin_layer<<<PGRID, 512, SMEM_BYTES>>>(dx1, 0,
                                          W1_0, b1_0, g0, be0, m0, v0, W2_0, b2_0);
    for (int i = 1; i < 4; i++) {
        const float* Xin = (i % 2 == 1) ? dx1 : dx2;
        float* Xo = (i % 2 == 1) ? dx2 : dx1;
        int off = i - 1;
        agg_k<<<aggGrid, 256>>>(Xin);
        gin_layer<<<PGRID, 512, SMEM_BYTES>>>(Xo, i * 128,
                                              W1s + off * 16384, b1s + off * 128,
                                              gs + off * 128, bes + off * 128,
                                              ms + off * 128, vs + off * 128,
                                              W2s + off * 16384, b2s + off * 128);
    }
    readout_k<<<1, 320>>>(Wll, bll, out);
}